// round 10
// baseline (speedup 1.0000x reference)
#include <cuda_runtime.h>
#include <cuda_bf16.h>
#include <cstdint>

// ============================================================================
// MemristorLinear: out[B,OUT] = x[B,IN] @ W[OUT,IN]^T + bias,
//                  W[o,i] = values[w_idx[o,i]]
// B=8192, IN=4096, OUT=4096, NVAL=1024.
//
// R10: tf32 path is MMA-issue-bound (134M HMMA @ ~14cyc eff, invariant to
// occupancy/BK). Switch to bf16 m16n8k16 (2048 MACs/instr) with 2-plane
// split:  x = x1 + x2,  w = w1 + w2  (x1=bf16(x), x2=bf16(x-x1)),
//   c += x1*w1 + x1*w2 + x2*w1   (drop x2*w2, ~4e-6 rel)
// -> 0.75x MMA instructions vs tf32. One fp32 accumulator for all 3 products.
// ============================================================================

#define B_DIM   8192
#define IN_DIM  4096
#define OUT_DIM 4096

#define BM 128
#define BN 128
#define BK 32
#define STAGES 3
#define KITERS (IN_DIM / BK)     // 128
#define THREADS 256

#define ROWB 80                            // smem bytes/row: 64 data + 16 pad
#define PLANE_BYTES (128 * ROWB)           // 10240
#define STAGE_BYTES (4 * PLANE_BYTES)      // 40960 (A1,A2,B1,B2)
#define SMEM_BYTES  (STAGES * STAGE_BYTES) // 122880

// Scratch (allocation-free rule: __device__ globals), bf16 planes
__device__ uint16_t g_X1[(size_t)B_DIM * IN_DIM];
__device__ uint16_t g_X2[(size_t)B_DIM * IN_DIM];
__device__ uint16_t g_W1[(size_t)OUT_DIM * IN_DIM];
__device__ uint16_t g_W2[(size_t)OUT_DIM * IN_DIM];
__device__ uint16_t g_v1[1024];
__device__ uint16_t g_v2[1024];
__device__ int g_idx_is64;

// ---------------------------------------------------------------------------
// helpers
// ---------------------------------------------------------------------------
__device__ __forceinline__ uint32_t smem_u32(const void* p) {
    uint32_t a;
    asm("{ .reg .u64 t; cvta.to.shared.u64 t, %1; cvt.u32.u64 %0, t; }"
        : "=r"(a) : "l"(p));
    return a;
}

__device__ __forceinline__ void cp_async16(uint32_t s, const void* g) {
    asm volatile("cp.async.cg.shared.global [%0], [%1], 16;\n" :: "r"(s), "l"(g));
}

// D += A*B : m16n8k16 bf16 x bf16 -> f32
__device__ __forceinline__ void mma_bf16(float* c, const uint32_t* a,
                                         const uint32_t* b) {
    asm volatile(
        "mma.sync.aligned.m16n8k16.row.col.f32.bf16.bf16.f32 "
        "{%0,%1,%2,%3}, {%4,%5,%6,%7}, {%8,%9}, {%0,%1,%2,%3};"
        : "+f"(c[0]), "+f"(c[1]), "+f"(c[2]), "+f"(c[3])
        : "r"(a[0]), "r"(a[1]), "r"(a[2]), "r"(a[3]), "r"(b[0]), "r"(b[1]));
}

// split v into bf16 hi + bf16 lo (lo = bf16(v - hi))
__device__ __forceinline__ void bf16_split(float v, uint16_t& hi, uint16_t& lo) {
    __nv_bfloat16 h = __float2bfloat16(v);
    __nv_bfloat16 l = __float2bfloat16(v - __bfloat162float(h));
    hi = *reinterpret_cast<uint16_t*>(&h);
    lo = *reinterpret_cast<uint16_t*>(&l);
}

// ---------------------------------------------------------------------------
// Pre-pass 0: detect w_idx dtype (indices < 1024 -> int64 odd words all 0)
// ---------------------------------------------------------------------------
__global__ void mml_detect_idx(const int* __restrict__ w32) {
    int nz = 0;
    #pragma unroll
    for (int i = 0; i < 64; i++) nz |= w32[2 * i + 1];
    g_idx_is64 = (nz == 0) ? 1 : 0;
}

// ---------------------------------------------------------------------------
// Pre-pass 1: split the 1024-entry codebook into bf16 hi/lo tables
// ---------------------------------------------------------------------------
__global__ void mml_split_vals(const float* __restrict__ values) {
    int t = threadIdx.x;
    uint16_t hi, lo;
    bf16_split(values[t], hi, lo);
    g_v1[t] = hi;
    g_v2[t] = lo;
}

// ---------------------------------------------------------------------------
// Pre-pass 2: split x into bf16 planes g_X1/g_X2
// ---------------------------------------------------------------------------
__global__ void mml_split_x(const float4* __restrict__ x, int n4) {
    int t = blockIdx.x * blockDim.x + threadIdx.x;
    if (t >= n4) return;
    float4 v = x[t];
    ushort4 a, b;
    bf16_split(v.x, a.x, b.x);
    bf16_split(v.y, a.y, b.y);
    bf16_split(v.z, a.z, b.z);
    bf16_split(v.w, a.w, b.w);
    reinterpret_cast<ushort4*>(g_X1)[t] = a;
    reinterpret_cast<ushort4*>(g_X2)[t] = b;
}

// ---------------------------------------------------------------------------
// Pre-pass 3: gather bf16 W planes from the codebook
// ---------------------------------------------------------------------------
__global__ void mml_gather_w(const void* __restrict__ widx, int n4) {
    __shared__ uint16_t s1[1024], s2[1024];
    for (int i = threadIdx.x; i < 1024; i += blockDim.x) {
        s1[i] = g_v1[i];
        s2[i] = g_v2[i];
    }
    __syncthreads();
    int t = blockIdx.x * blockDim.x + threadIdx.x;
    if (t >= n4) return;
    int i0, i1, i2, i3;
    if (g_idx_is64) {
        const longlong2* p = reinterpret_cast<const longlong2*>(widx) + 2 * t;
        longlong2 a = p[0];
        longlong2 b = p[1];
        i0 = (int)a.x; i1 = (int)a.y; i2 = (int)b.x; i3 = (int)b.y;
    } else {
        int4 a = reinterpret_cast<const int4*>(widx)[t];
        i0 = a.x; i1 = a.y; i2 = a.z; i3 = a.w;
    }
    ushort4 a, b;
    a.x = s1[i0]; a.y = s1[i1]; a.z = s1[i2]; a.w = s1[i3];
    b.x = s2[i0]; b.y = s2[i1]; b.z = s2[i2]; b.w = s2[i3];
    reinterpret_cast<ushort4*>(g_W1)[t] = a;
    reinterpret_cast<ushort4*>(g_W2)[t] = b;
}

// ---------------------------------------------------------------------------
// Main GEMM: 128x128 CTA tile, 8 warps (2 M x 4 N), 64x32 warp tiles,
// bf16 m16n8k16, BK=32 (2 k16 chunks per stage), 3 products -> 1 accumulator.
// ---------------------------------------------------------------------------
__global__ __launch_bounds__(THREADS, 1)
void mml_gemm(const float* __restrict__ bias, float* __restrict__ out) {
    extern __shared__ char sm[];
    const int tid  = threadIdx.x;
    const int lane = tid & 31;
    const int wid  = tid >> 5;
    const int wm   = wid & 1;        // 2 warps in M
    const int wn   = wid >> 1;       // 4 warps in N
    const int m0   = blockIdx.y * BM;
    const int n0   = blockIdx.x * BN;

    const uint32_t smem_base = smem_u32(sm);
    const int lr = lane >> 2;        // 0..7
    const int lc = lane & 3;         // 0..3

    float c[4][4][4];
    #pragma unroll
    for (int mt = 0; mt < 4; mt++)
        #pragma unroll
        for (int nt = 0; nt < 4; nt++)
            #pragma unroll
            for (int r = 0; r < 4; r++) c[mt][nt][r] = 0.0f;

    // ---- stage loader: 4 planes (A1,A2,B1,B2), 128 rows x 64B each ----
    auto load_stage = [&](int ks, int slot) {
        uint32_t base = smem_base + (uint32_t)(slot * STAGE_BYTES);
        const char* gp[4];
        gp[0] = (const char*)(g_X1 + (size_t)m0 * IN_DIM + (size_t)ks * BK);
        gp[1] = (const char*)(g_X2 + (size_t)m0 * IN_DIM + (size_t)ks * BK);
        gp[2] = (const char*)(g_W1 + (size_t)n0 * IN_DIM + (size_t)ks * BK);
        gp[3] = (const char*)(g_W2 + (size_t)n0 * IN_DIM + (size_t)ks * BK);
        #pragma unroll
        for (int p = 0; p < 4; p++) {
            #pragma unroll
            for (int q = tid; q < 512; q += THREADS) {   // 128 rows x 4 chunks
                int row = q >> 2, ch = q & 3;
                cp_async16(base + (uint32_t)(p * PLANE_BYTES + row * ROWB + ch * 16),
                           gp[p] + (size_t)row * (IN_DIM * 2) + ch * 16);
            }
        }
    };

    load_stage(0, 0);
    asm volatile("cp.async.commit_group;" ::: "memory");
    load_stage(1, 1);
    asm volatile("cp.async.commit_group;" ::: "memory");

    for (int i = 0; i < KITERS; i++) {
        asm volatile("cp.async.wait_group 1;" ::: "memory");
        __syncthreads();

        if (i + 2 < KITERS) load_stage(i + 2, (i + 2) % STAGES);
        asm volatile("cp.async.commit_group;" ::: "memory");

        const char* sA1 = sm + (i % STAGES) * STAGE_BYTES;
        const char* sA2 = sA1 + PLANE_BYTES;
        const char* sB1 = sA2 + PLANE_BYTES;
        const char* sB2 = sB1 + PLANE_BYTES;

        #pragma unroll
        for (int kk = 0; kk < 2; kk++) {          // two k16 chunks (32B each)
            const int kb = kk * 32 + lc * 4;
            uint32_t a1[4][4], a2[4][4], b1[4][2], b2[4][2];
            #pragma unroll
            for (int mt = 0; mt < 4; mt++) {
                int row = wm * 64 + mt * 16 + lr;
                int o0 = row * ROWB + kb;
                int o1 = o0 + 8 * ROWB;
                a1[mt][0] = *(const uint32_t*)(sA1 + o0);
                a1[mt][1] = *(const uint32_t*)(sA1 + o1);
                a1[mt][2] = *(const uint32_t*)(sA1 + o0 + 16);
                a1[mt][3] = *(const uint32_t*)(sA1 + o1 + 16);
                a2[mt][0] = *(const uint32_t*)(sA2 + o0);
                a2[mt][1] = *(const uint32_t*)(sA2 + o1);
                a2[mt][2] = *(const uint32_t*)(sA2 + o0 + 16);
                a2[mt][3] = *(const uint32_t*)(sA2 + o1 + 16);
            }
            #pragma unroll
            for (int nt = 0; nt < 4; nt++) {
                int nrow = wn * 32 + nt * 8 + lr;
                int ob = nrow * ROWB + kb;
                b1[nt][0] = *(const uint32_t*)(sB1 + ob);
                b1[nt][1] = *(const uint32_t*)(sB1 + ob + 16);
                b2[nt][0] = *(const uint32_t*)(sB2 + ob);
                b2[nt][1] = *(const uint32_t*)(sB2 + ob + 16);
            }
            #pragma unroll
            for (int mt = 0; mt < 4; mt++)
                #pragma unroll
                for (int nt = 0; nt < 4; nt++) {
                    mma_bf16(c[mt][nt], a1[mt], b1[nt]);
                    mma_bf16(c[mt][nt], a1[mt], b2[nt]);
                    mma_bf16(c[mt][nt], a2[mt], b1[nt]);
                }
        }
    }

    // ---- epilogue: add bias, write float2 coalesced ----
    float2 bb[4];
    #pragma unroll
    for (int nt = 0; nt < 4; nt++) {
        int cn = n0 + wn * 32 + nt * 8 + lc * 2;
        bb[nt].x = __ldg(bias + cn);
        bb[nt].y = __ldg(bias + cn + 1);
    }
    #pragma unroll
    for (int mt = 0; mt < 4; mt++) {
        int r0 = m0 + wm * 64 + mt * 16 + lr;
        int r1 = r0 + 8;
        float* o0 = out + (size_t)r0 * OUT_DIM;
        float* o1 = out + (size_t)r1 * OUT_DIM;
        #pragma unroll
        for (int nt = 0; nt < 4; nt++) {
            int cn = n0 + wn * 32 + nt * 8 + lc * 2;
            float2 v0, v1;
            v0.x = c[mt][nt][0] + bb[nt].x;
            v0.y = c[mt][nt][1] + bb[nt].y;
            v1.x = c[mt][nt][2] + bb[nt].x;
            v1.y = c[mt][nt][3] + bb[nt].y;
            *reinterpret_cast<float2*>(o0 + cn) = v0;
            *reinterpret_cast<float2*>(o1 + cn) = v1;
        }
    }
}

// ---------------------------------------------------------------------------
// kernel_launch — inputs identified by element count (order-proof):
//   x: 33554432, values: 1024, bias: 4096, w_idx: 16777216
// ---------------------------------------------------------------------------
extern "C" void kernel_launch(void* const* d_in, const int* in_sizes, int n_in,
                              void* d_out, int out_size) {
    const float* x      = nullptr;
    const float* values = nullptr;
    const float* bias   = nullptr;
    const void*  widx   = nullptr;

    for (int i = 0; i < n_in; i++) {
        switch (in_sizes[i]) {
            case 33554432: x      = (const float*)d_in[i]; break;
            case 1024:     values = (const float*)d_in[i]; break;
            case 4096:     bias   = (const float*)d_in[i]; break;
            case 16777216: widx   = d_in[i];               break;
            default: break;
        }
    }
    float* out = (float*)d_out;

    int nx4 = (B_DIM * IN_DIM) / 4;        // 8388608
    int nw4 = (OUT_DIM * IN_DIM) / 4;      // 4194304

    mml_detect_idx<<<1, 1>>>((const int*)widx);
    mml_split_vals<<<1, 1024>>>(values);
    mml_split_x<<<nx4 / 256, 256>>>((const float4*)x, nx4);
    mml_gather_w<<<nw4 / 256, 256>>>(widx, nw4);

    cudaFuncSetAttribute(mml_gemm, cudaFuncAttributeMaxDynamicSharedMemorySize,
                         SMEM_BYTES);
    dim3 grid(OUT_DIM / BN, B_DIM / BM);   // (32, 64)
    mml_gemm<<<grid, THREADS, SMEM_BYTES>>>(bias, out);
}

// round 11
// speedup vs baseline: 2.5383x; 2.5383x over previous
#include <cuda_runtime.h>
#include <cuda_fp16.h>
#include <cstdint>

// ============================================================================
// MemristorLinear: out[B,OUT] = x[B,IN] @ W[OUT,IN]^T + bias,
//                  W[o,i] = values[w_idx[o,i]]
// B=8192, IN=4096, OUT=4096, NVAL=1024.
//
// R11: calibration across tf32(134M instr, 1550us) and bf16-k16x3(201M,
// ~2500us) shows the GEMM is MMA-ISSUE-bound at ~12us/M-instr, with k16
// costing the same slot as k8. fp16 has the SAME 11-bit mantissa as tf32
// -> single fp16 m16n8k16 product = 67M instr = ~800-900us GEMM at tf32
// accuracy (~3e-4). CTA 128x128, 8 warps (2Mx4N), 64x32 warp tiles, BK=32,
// 3-stage cp.async, 2 CTAs/SM.
// ============================================================================

#define B_DIM   8192
#define IN_DIM  4096
#define OUT_DIM 4096

#define BM 128
#define BN 128
#define BK 32
#define STAGES 3
#define KITERS (IN_DIM / BK)     // 128
#define THREADS 256

#define ROWB 80                            // smem bytes/row: 64 data + 16 pad
#define PLANE_BYTES (128 * ROWB)           // 10240
#define STAGE_BYTES (2 * PLANE_BYTES)      // 20480 (A, B)
#define SMEM_BYTES  (STAGES * STAGE_BYTES) // 61440 -> 2 CTAs/SM = 120 KB

// Scratch (allocation-free rule: __device__ globals), fp16
__device__ uint16_t g_X[(size_t)B_DIM * IN_DIM];    // 64 MB fp16 x
__device__ uint16_t g_W[(size_t)OUT_DIM * IN_DIM];  // 32 MB fp16 gathered W
__device__ uint16_t g_v16[1024];                    // fp16 codebook
__device__ int g_idx_is64;

// ---------------------------------------------------------------------------
// helpers
// ---------------------------------------------------------------------------
__device__ __forceinline__ uint32_t smem_u32(const void* p) {
    uint32_t a;
    asm("{ .reg .u64 t; cvta.to.shared.u64 t, %1; cvt.u32.u64 %0, t; }"
        : "=r"(a) : "l"(p));
    return a;
}

__device__ __forceinline__ void cp_async16(uint32_t s, const void* g) {
    asm volatile("cp.async.cg.shared.global [%0], [%1], 16;\n" :: "r"(s), "l"(g));
}

// D += A*B : m16n8k16 f16 x f16 -> f32
__device__ __forceinline__ void mma_f16(float* c, const uint32_t* a,
                                        const uint32_t* b) {
    asm volatile(
        "mma.sync.aligned.m16n8k16.row.col.f32.f16.f16.f32 "
        "{%0,%1,%2,%3}, {%4,%5,%6,%7}, {%8,%9}, {%0,%1,%2,%3};"
        : "+f"(c[0]), "+f"(c[1]), "+f"(c[2]), "+f"(c[3])
        : "r"(a[0]), "r"(a[1]), "r"(a[2]), "r"(a[3]), "r"(b[0]), "r"(b[1]));
}

__device__ __forceinline__ uint16_t f2h(float v) {
    __half h = __float2half_rn(v);
    return *reinterpret_cast<uint16_t*>(&h);
}

// ---------------------------------------------------------------------------
// Pre-pass 0: detect w_idx dtype (indices < 1024 -> int64 odd words all 0)
// ---------------------------------------------------------------------------
__global__ void mml_detect_idx(const int* __restrict__ w32) {
    int nz = 0;
    #pragma unroll
    for (int i = 0; i < 64; i++) nz |= w32[2 * i + 1];
    g_idx_is64 = (nz == 0) ? 1 : 0;
}

// ---------------------------------------------------------------------------
// Pre-pass 1: convert the 1024-entry codebook to fp16
// ---------------------------------------------------------------------------
__global__ void mml_conv_vals(const float* __restrict__ values) {
    int t = threadIdx.x;
    g_v16[t] = f2h(values[t]);
}

// ---------------------------------------------------------------------------
// Pre-pass 2: convert x to fp16 into g_X
// ---------------------------------------------------------------------------
__global__ void mml_conv_x(const float4* __restrict__ x, int n4) {
    int t = blockIdx.x * blockDim.x + threadIdx.x;
    if (t >= n4) return;
    float4 v = x[t];
    ushort4 o;
    o.x = f2h(v.x); o.y = f2h(v.y); o.z = f2h(v.z); o.w = f2h(v.w);
    reinterpret_cast<ushort4*>(g_X)[t] = o;
}

// ---------------------------------------------------------------------------
// Pre-pass 3: gather fp16 W from the codebook
// ---------------------------------------------------------------------------
__global__ void mml_gather_w(const void* __restrict__ widx, int n4) {
    __shared__ uint16_t sv[1024];
    for (int i = threadIdx.x; i < 1024; i += blockDim.x) sv[i] = g_v16[i];
    __syncthreads();
    int t = blockIdx.x * blockDim.x + threadIdx.x;
    if (t >= n4) return;
    int i0, i1, i2, i3;
    if (g_idx_is64) {
        const longlong2* p = reinterpret_cast<const longlong2*>(widx) + 2 * t;
        longlong2 a = p[0];
        longlong2 b = p[1];
        i0 = (int)a.x; i1 = (int)a.y; i2 = (int)b.x; i3 = (int)b.y;
    } else {
        int4 a = reinterpret_cast<const int4*>(widx)[t];
        i0 = a.x; i1 = a.y; i2 = a.z; i3 = a.w;
    }
    ushort4 o;
    o.x = sv[i0]; o.y = sv[i1]; o.z = sv[i2]; o.w = sv[i3];
    reinterpret_cast<ushort4*>(g_W)[t] = o;
}

// ---------------------------------------------------------------------------
// Main GEMM: 128x128 CTA tile, 8 warps (2 M x 4 N), 64x32 warp tiles,
// fp16 m16n8k16, BK=32 (2 k16 chunks per stage), 2 CTAs/SM.
// ---------------------------------------------------------------------------
__global__ __launch_bounds__(THREADS, 2)
void mml_gemm(const float* __restrict__ bias, float* __restrict__ out) {
    extern __shared__ char sm[];
    const int tid  = threadIdx.x;
    const int lane = tid & 31;
    const int wid  = tid >> 5;
    const int wm   = wid & 1;        // 2 warps in M
    const int wn   = wid >> 1;       // 4 warps in N
    const int m0   = blockIdx.y * BM;
    const int n0   = blockIdx.x * BN;

    const uint32_t smem_base = smem_u32(sm);
    const int lr = lane >> 2;        // 0..7
    const int lc = lane & 3;         // 0..3

    float c[4][4][4];
    #pragma unroll
    for (int mt = 0; mt < 4; mt++)
        #pragma unroll
        for (int nt = 0; nt < 4; nt++)
            #pragma unroll
            for (int r = 0; r < 4; r++) c[mt][nt][r] = 0.0f;

    // ---- stage loader: A + B planes, 128 rows x 64B each (fp16) ----
    auto load_stage = [&](int ks, int slot) {
        uint32_t base = smem_base + (uint32_t)(slot * STAGE_BYTES);
        const char* ga = (const char*)(g_X + (size_t)m0 * IN_DIM + (size_t)ks * BK);
        const char* gb = (const char*)(g_W + (size_t)n0 * IN_DIM + (size_t)ks * BK);
        #pragma unroll
        for (int q = tid; q < 512; q += THREADS) {      // 128 rows x 4 chunks
            int row = q >> 2, ch = q & 3;
            cp_async16(base + (uint32_t)(row * ROWB + ch * 16),
                       ga + (size_t)row * (IN_DIM * 2) + ch * 16);
        }
        #pragma unroll
        for (int q = tid; q < 512; q += THREADS) {
            int row = q >> 2, ch = q & 3;
            cp_async16(base + (uint32_t)(PLANE_BYTES + row * ROWB + ch * 16),
                       gb + (size_t)row * (IN_DIM * 2) + ch * 16);
        }
    };

    load_stage(0, 0);
    asm volatile("cp.async.commit_group;" ::: "memory");
    load_stage(1, 1);
    asm volatile("cp.async.commit_group;" ::: "memory");

    for (int i = 0; i < KITERS; i++) {
        asm volatile("cp.async.wait_group 1;" ::: "memory");
        __syncthreads();

        if (i + 2 < KITERS) load_stage(i + 2, (i + 2) % STAGES);
        asm volatile("cp.async.commit_group;" ::: "memory");

        const char* sA = sm + (i % STAGES) * STAGE_BYTES;
        const char* sB = sA + PLANE_BYTES;

        #pragma unroll
        for (int kk = 0; kk < 2; kk++) {          // two k16 chunks (32B each)
            const int kb = kk * 32 + lc * 4;
            uint32_t af[4][4], bf[4][2];
            #pragma unroll
            for (int mt = 0; mt < 4; mt++) {
                int row = wm * 64 + mt * 16 + lr;
                int o0 = row * ROWB + kb;
                int o1 = o0 + 8 * ROWB;
                af[mt][0] = *(const uint32_t*)(sA + o0);
                af[mt][1] = *(const uint32_t*)(sA + o1);
                af[mt][2] = *(const uint32_t*)(sA + o0 + 16);
                af[mt][3] = *(const uint32_t*)(sA + o1 + 16);
            }
            #pragma unroll
            for (int nt = 0; nt < 4; nt++) {
                int nrow = wn * 32 + nt * 8 + lr;
                int ob = nrow * ROWB + kb;
                bf[nt][0] = *(const uint32_t*)(sB + ob);
                bf[nt][1] = *(const uint32_t*)(sB + ob + 16);
            }
            #pragma unroll
            for (int mt = 0; mt < 4; mt++)
                #pragma unroll
                for (int nt = 0; nt < 4; nt++)
                    mma_f16(c[mt][nt], af[mt], bf[nt]);
        }
    }

    // ---- epilogue: add bias, write float2 coalesced ----
    float2 bb[4];
    #pragma unroll
    for (int nt = 0; nt < 4; nt++) {
        int cn = n0 + wn * 32 + nt * 8 + lc * 2;
        bb[nt].x = __ldg(bias + cn);
        bb[nt].y = __ldg(bias + cn + 1);
    }
    #pragma unroll
    for (int mt = 0; mt < 4; mt++) {
        int r0 = m0 + wm * 64 + mt * 16 + lr;
        int r1 = r0 + 8;
        float* o0 = out + (size_t)r0 * OUT_DIM;
        float* o1 = out + (size_t)r1 * OUT_DIM;
        #pragma unroll
        for (int nt = 0; nt < 4; nt++) {
            int cn = n0 + wn * 32 + nt * 8 + lc * 2;
            float2 v0, v1;
            v0.x = c[mt][nt][0] + bb[nt].x;
            v0.y = c[mt][nt][1] + bb[nt].y;
            v1.x = c[mt][nt][2] + bb[nt].x;
            v1.y = c[mt][nt][3] + bb[nt].y;
            *reinterpret_cast<float2*>(o0 + cn) = v0;
            *reinterpret_cast<float2*>(o1 + cn) = v1;
        }
    }
}

// ---------------------------------------------------------------------------
// kernel_launch — inputs identified by element count (order-proof):
//   x: 33554432, values: 1024, bias: 4096, w_idx: 16777216
// ---------------------------------------------------------------------------
extern "C" void kernel_launch(void* const* d_in, const int* in_sizes, int n_in,
                              void* d_out, int out_size) {
    const float* x      = nullptr;
    const float* values = nullptr;
    const float* bias   = nullptr;
    const void*  widx   = nullptr;

    for (int i = 0; i < n_in; i++) {
        switch (in_sizes[i]) {
            case 33554432: x      = (const float*)d_in[i]; break;
            case 1024:     values = (const float*)d_in[i]; break;
            case 4096:     bias   = (const float*)d_in[i]; break;
            case 16777216: widx   = d_in[i];               break;
            default: break;
        }
    }
    float* out = (float*)d_out;

    int nx4 = (B_DIM * IN_DIM) / 4;        // 8388608
    int nw4 = (OUT_DIM * IN_DIM) / 4;      // 4194304

    mml_detect_idx<<<1, 1>>>((const int*)widx);
    mml_conv_vals<<<1, 1024>>>(values);
    mml_conv_x<<<nx4 / 256, 256>>>((const float4*)x, nx4);
    mml_gather_w<<<nw4 / 256, 256>>>(widx, nw4);

    cudaFuncSetAttribute(mml_gemm, cudaFuncAttributeMaxDynamicSharedMemorySize,
                         SMEM_BYTES);
    dim3 grid(OUT_DIM / BN, B_DIM / BM);   // (32, 64)
    mml_gemm<<<grid, THREADS, SMEM_BYTES>>>(bias, out);
}

// round 12
// speedup vs baseline: 2.5862x; 1.0189x over previous
#include <cuda_runtime.h>
#include <cuda_fp16.h>
#include <cstdint>

// ============================================================================
// MemristorLinear: out[B,OUT] = x[B,IN] @ W[OUT,IN]^T + bias,
//                  W[o,i] = values[w_idx[o,i]]
// B=8192, IN=4096, OUT=4096, NVAL=1024.
//
// R12: fp16 m16n8k16 (same mantissa as tf32, half the MMA instructions).
// Widen to CTA 128x256, 8 warps (2Mx4N), 64x64 warp tiles -> LDS/MMA ratio
// 1.0 (was 1.5 at 64x32), amortizing loop/barrier overhead now that MMA
// count is halved. 3-stage cp.async, BK=32, 1 CTA/SM (90KB smem).
// ============================================================================

#define B_DIM   8192
#define IN_DIM  4096
#define OUT_DIM 4096

#define BM 128
#define BN 256
#define BK 32
#define STAGES 3
#define KITERS (IN_DIM / BK)     // 128
#define THREADS 256

#define ROWB 80                            // smem bytes/row: 64 data + 16 pad
#define A_BYTES (128 * ROWB)               // 10240
#define B_BYTES (256 * ROWB)               // 20480
#define STAGE_BYTES (A_BYTES + B_BYTES)    // 30720
#define SMEM_BYTES  (STAGES * STAGE_BYTES) // 92160

// Scratch (allocation-free rule: __device__ globals), fp16
__device__ uint16_t g_X[(size_t)B_DIM * IN_DIM];    // 64 MB fp16 x
__device__ uint16_t g_W[(size_t)OUT_DIM * IN_DIM];  // 32 MB fp16 gathered W
__device__ uint16_t g_v16[1024];                    // fp16 codebook
__device__ int g_idx_is64;

// ---------------------------------------------------------------------------
// helpers
// ---------------------------------------------------------------------------
__device__ __forceinline__ uint32_t smem_u32(const void* p) {
    uint32_t a;
    asm("{ .reg .u64 t; cvta.to.shared.u64 t, %1; cvt.u32.u64 %0, t; }"
        : "=r"(a) : "l"(p));
    return a;
}

__device__ __forceinline__ void cp_async16(uint32_t s, const void* g) {
    asm volatile("cp.async.cg.shared.global [%0], [%1], 16;\n" :: "r"(s), "l"(g));
}

// D += A*B : m16n8k16 f16 x f16 -> f32
__device__ __forceinline__ void mma_f16(float* c, const uint32_t* a,
                                        const uint32_t* b) {
    asm volatile(
        "mma.sync.aligned.m16n8k16.row.col.f32.f16.f16.f32 "
        "{%0,%1,%2,%3}, {%4,%5,%6,%7}, {%8,%9}, {%0,%1,%2,%3};"
        : "+f"(c[0]), "+f"(c[1]), "+f"(c[2]), "+f"(c[3])
        : "r"(a[0]), "r"(a[1]), "r"(a[2]), "r"(a[3]), "r"(b[0]), "r"(b[1]));
}

__device__ __forceinline__ uint16_t f2h(float v) {
    __half h = __float2half_rn(v);
    return *reinterpret_cast<uint16_t*>(&h);
}

// ---------------------------------------------------------------------------
// Pre-pass 0: detect w_idx dtype (indices < 1024 -> int64 odd words all 0)
// ---------------------------------------------------------------------------
__global__ void mml_detect_idx(const int* __restrict__ w32) {
    int nz = 0;
    #pragma unroll
    for (int i = 0; i < 64; i++) nz |= w32[2 * i + 1];
    g_idx_is64 = (nz == 0) ? 1 : 0;
}

// ---------------------------------------------------------------------------
// Pre-pass 1: convert the 1024-entry codebook to fp16
// ---------------------------------------------------------------------------
__global__ void mml_conv_vals(const float* __restrict__ values) {
    int t = threadIdx.x;
    g_v16[t] = f2h(values[t]);
}

// ---------------------------------------------------------------------------
// Pre-pass 2: convert x to fp16 into g_X
// ---------------------------------------------------------------------------
__global__ void mml_conv_x(const float4* __restrict__ x, int n4) {
    int t = blockIdx.x * blockDim.x + threadIdx.x;
    if (t >= n4) return;
    float4 v = x[t];
    ushort4 o;
    o.x = f2h(v.x); o.y = f2h(v.y); o.z = f2h(v.z); o.w = f2h(v.w);
    reinterpret_cast<ushort4*>(g_X)[t] = o;
}

// ---------------------------------------------------------------------------
// Pre-pass 3: gather fp16 W from the codebook
// ---------------------------------------------------------------------------
__global__ void mml_gather_w(const void* __restrict__ widx, int n4) {
    __shared__ uint16_t sv[1024];
    for (int i = threadIdx.x; i < 1024; i += blockDim.x) sv[i] = g_v16[i];
    __syncthreads();
    int t = blockIdx.x * blockDim.x + threadIdx.x;
    if (t >= n4) return;
    int i0, i1, i2, i3;
    if (g_idx_is64) {
        const longlong2* p = reinterpret_cast<const longlong2*>(widx) + 2 * t;
        longlong2 a = p[0];
        longlong2 b = p[1];
        i0 = (int)a.x; i1 = (int)a.y; i2 = (int)b.x; i3 = (int)b.y;
    } else {
        int4 a = reinterpret_cast<const int4*>(widx)[t];
        i0 = a.x; i1 = a.y; i2 = a.z; i3 = a.w;
    }
    ushort4 o;
    o.x = sv[i0]; o.y = sv[i1]; o.z = sv[i2]; o.w = sv[i3];
    reinterpret_cast<ushort4*>(g_W)[t] = o;
}

// ---------------------------------------------------------------------------
// Main GEMM: 128x256 CTA tile, 8 warps (2 M x 4 N), 64x64 warp tiles,
// fp16 m16n8k16, BK=32 (2 k16 chunks per stage).
// ---------------------------------------------------------------------------
__global__ __launch_bounds__(THREADS, 1)
void mml_gemm(const float* __restrict__ bias, float* __restrict__ out) {
    extern __shared__ char sm[];
    const int tid  = threadIdx.x;
    const int lane = tid & 31;
    const int wid  = tid >> 5;
    const int wm   = wid & 1;        // 2 warps in M
    const int wn   = wid >> 1;       // 4 warps in N
    const int m0   = blockIdx.y * BM;
    const int n0   = blockIdx.x * BN;

    const uint32_t smem_base = smem_u32(sm);
    const int lr = lane >> 2;        // 0..7
    const int lc = lane & 3;         // 0..3

    // accumulators: 4 m-tiles x 8 n-tiles x 4 regs = 128
    float c[4][8][4];
    #pragma unroll
    for (int mt = 0; mt < 4; mt++)
        #pragma unroll
        for (int nt = 0; nt < 8; nt++)
            #pragma unroll
            for (int r = 0; r < 4; r++) c[mt][nt][r] = 0.0f;

    // ---- stage loader: A (128 rows) + B (256 rows), 64B data per row ----
    auto load_stage = [&](int ks, int slot) {
        uint32_t base = smem_base + (uint32_t)(slot * STAGE_BYTES);
        const char* ga = (const char*)(g_X + (size_t)m0 * IN_DIM + (size_t)ks * BK);
        const char* gb = (const char*)(g_W + (size_t)n0 * IN_DIM + (size_t)ks * BK);
        #pragma unroll
        for (int q = tid; q < 512; q += THREADS) {      // A: 128 rows x 4 chunks
            int row = q >> 2, ch = q & 3;
            cp_async16(base + (uint32_t)(row * ROWB + ch * 16),
                       ga + (size_t)row * (IN_DIM * 2) + ch * 16);
        }
        #pragma unroll
        for (int q = tid; q < 1024; q += THREADS) {     // B: 256 rows x 4 chunks
            int row = q >> 2, ch = q & 3;
            cp_async16(base + (uint32_t)(A_BYTES + row * ROWB + ch * 16),
                       gb + (size_t)row * (IN_DIM * 2) + ch * 16);
        }
    };

    load_stage(0, 0);
    asm volatile("cp.async.commit_group;" ::: "memory");
    load_stage(1, 1);
    asm volatile("cp.async.commit_group;" ::: "memory");

    for (int i = 0; i < KITERS; i++) {
        asm volatile("cp.async.wait_group 1;" ::: "memory");
        __syncthreads();

        if (i + 2 < KITERS) load_stage(i + 2, (i + 2) % STAGES);
        asm volatile("cp.async.commit_group;" ::: "memory");

        const char* sA = sm + (i % STAGES) * STAGE_BYTES;
        const char* sB = sA + A_BYTES;

        #pragma unroll
        for (int kk = 0; kk < 2; kk++) {          // two k16 chunks (32B each)
            const int kb = kk * 32 + lc * 4;
            uint32_t af[4][4], bf[8][2];
            #pragma unroll
            for (int mt = 0; mt < 4; mt++) {
                int row = wm * 64 + mt * 16 + lr;
                int o0 = row * ROWB + kb;
                int o1 = o0 + 8 * ROWB;
                af[mt][0] = *(const uint32_t*)(sA + o0);
                af[mt][1] = *(const uint32_t*)(sA + o1);
                af[mt][2] = *(const uint32_t*)(sA + o0 + 16);
                af[mt][3] = *(const uint32_t*)(sA + o1 + 16);
            }
            #pragma unroll
            for (int nt = 0; nt < 8; nt++) {
                int nrow = wn * 64 + nt * 8 + lr;
                int ob = nrow * ROWB + kb;
                bf[nt][0] = *(const uint32_t*)(sB + ob);
                bf[nt][1] = *(const uint32_t*)(sB + ob + 16);
            }
            #pragma unroll
            for (int mt = 0; mt < 4; mt++)
                #pragma unroll
                for (int nt = 0; nt < 8; nt++)
                    mma_f16(c[mt][nt], af[mt], bf[nt]);
        }
    }

    // ---- epilogue: add bias, write float2 coalesced ----
    float2 bb[8];
    #pragma unroll
    for (int nt = 0; nt < 8; nt++) {
        int cn = n0 + wn * 64 + nt * 8 + lc * 2;
        bb[nt].x = __ldg(bias + cn);
        bb[nt].y = __ldg(bias + cn + 1);
    }
    #pragma unroll
    for (int mt = 0; mt < 4; mt++) {
        int r0 = m0 + wm * 64 + mt * 16 + lr;
        int r1 = r0 + 8;
        float* o0 = out + (size_t)r0 * OUT_DIM;
        float* o1 = out + (size_t)r1 * OUT_DIM;
        #pragma unroll
        for (int nt = 0; nt < 8; nt++) {
            int cn = n0 + wn * 64 + nt * 8 + lc * 2;
            float2 v0, v1;
            v0.x = c[mt][nt][0] + bb[nt].x;
            v0.y = c[mt][nt][1] + bb[nt].y;
            v1.x = c[mt][nt][2] + bb[nt].x;
            v1.y = c[mt][nt][3] + bb[nt].y;
            *reinterpret_cast<float2*>(o0 + cn) = v0;
            *reinterpret_cast<float2*>(o1 + cn) = v1;
        }
    }
}

// ---------------------------------------------------------------------------
// kernel_launch — inputs identified by element count (order-proof):
//   x: 33554432, values: 1024, bias: 4096, w_idx: 16777216
// ---------------------------------------------------------------------------
extern "C" void kernel_launch(void* const* d_in, const int* in_sizes, int n_in,
                              void* d_out, int out_size) {
    const float* x      = nullptr;
    const float* values = nullptr;
    const float* bias   = nullptr;
    const void*  widx   = nullptr;

    for (int i = 0; i < n_in; i++) {
        switch (in_sizes[i]) {
            case 33554432: x      = (const float*)d_in[i]; break;
            case 1024:     values = (const float*)d_in[i]; break;
            case 4096:     bias   = (const float*)d_in[i]; break;
            case 16777216: widx   = d_in[i];               break;
            default: break;
        }
    }
    float* out = (float*)d_out;

    int nx4 = (B_DIM * IN_DIM) / 4;        // 8388608
    int nw4 = (OUT_DIM * IN_DIM) / 4;      // 4194304

    mml_detect_idx<<<1, 1>>>((const int*)widx);
    mml_conv_vals<<<1, 1024>>>(values);
    mml_conv_x<<<nx4 / 256, 256>>>((const float4*)x, nx4);
    mml_gather_w<<<nw4 / 256, 256>>>(widx, nw4);

    cudaFuncSetAttribute(mml_gemm, cudaFuncAttributeMaxDynamicSharedMemorySize,
                         SMEM_BYTES);
    dim3 grid(OUT_DIM / BN, B_DIM / BM);   // (16, 64)
    mml_gemm<<<grid, THREADS, SMEM_BYTES>>>(bias, out);
}